// round 5
// baseline (speedup 1.0000x reference)
#include <cuda_runtime.h>
#include <math.h>

#define NN 50000
#define EE 400000
#define FF 32
#define QE (EE / 4)
#define HALF_E (EE / 2)

typedef unsigned long long ull;

// ---------------- scratch (static device arrays; allocation-free) ----------------
__device__ __align__(128) float g_e1[(size_t)EE * FF];
__device__ __align__(128) float g_e2[(size_t)EE * FF];
__device__ __align__(128) float g_e3[(size_t)EE * FF];
__device__ __align__(128) float g_acc1[(size_t)NN * FF];
__device__ __align__(128) float g_acc2[(size_t)NN * FF];
__device__ __align__(128) float g_acc3[(size_t)NN * FF];
__device__ __align__(128) float g_cnt[NN];

// ---------------- f32x2 packed-FMA helpers ----------------
__device__ __forceinline__ void ffma2(ull& d, ull a, ull b) {
    asm("fma.rn.f32x2 %0, %1, %2, %0;" : "+l"(d) : "l"(a), "l"(b));
}
__device__ __forceinline__ ull pk2(float v) {
    ull r;
    asm("mov.b64 %0, {%1, %1};" : "=l"(r) : "f"(v));
    return r;
}

union V32 {
    float f[FF];
    ull u[FF / 2];
};
union V8 {
    float f[8];
    ull u[4];
};

// 4 edges share each weight load: 1 LDS.128 feeds 8 ffma2
__device__ __forceinline__ void fmarow4(V32& h0, V32& h1, V32& h2, V32& h3, ull v0, ull v1,
                                        ull v2, ull v3, const float* __restrict__ wr) {
#pragma unroll
    for (int j = 0; j < 8; j++) {
        ulonglong2 w = *(const ulonglong2*)(wr + j * 4);
        ffma2(h0.u[2 * j], v0, w.x);
        ffma2(h0.u[2 * j + 1], v0, w.y);
        ffma2(h1.u[2 * j], v1, w.x);
        ffma2(h1.u[2 * j + 1], v1, w.y);
        ffma2(h2.u[2 * j], v2, w.x);
        ffma2(h2.u[2 * j + 1], v2, w.y);
        ffma2(h3.u[2 * j], v3, w.x);
        ffma2(h3.u[2 * j + 1], v3, w.y);
    }
}

__device__ __forceinline__ void seg32q(V32& h0, V32& h1, V32& h2, V32& h3,
                                       const float* __restrict__ s0,
                                       const float* __restrict__ s1,
                                       const float* __restrict__ s2,
                                       const float* __restrict__ s3,
                                       const float* __restrict__ ws) {
#pragma unroll
    for (int k = 0; k < FF; k += 4) {
        float4 a = *(const float4*)(s0 + k);
        float4 b = *(const float4*)(s1 + k);
        float4 c = *(const float4*)(s2 + k);
        float4 d = *(const float4*)(s3 + k);
        fmarow4(h0, h1, h2, h3, pk2(a.x), pk2(b.x), pk2(c.x), pk2(d.x), ws + (k + 0) * FF);
        fmarow4(h0, h1, h2, h3, pk2(a.y), pk2(b.y), pk2(c.y), pk2(d.y), ws + (k + 1) * FF);
        fmarow4(h0, h1, h2, h3, pk2(a.z), pk2(b.z), pk2(c.z), pk2(d.z), ws + (k + 2) * FF);
        fmarow4(h0, h1, h2, h3, pk2(a.w), pk2(b.w), pk2(c.w), pk2(d.w), ws + (k + 3) * FF);
    }
}

// ---------------- misc helpers ----------------
__device__ __forceinline__ void cpsh(float* dst, const float* src, int n, int tid, int nt) {
    for (int i = tid; i < n; i += nt) dst[i] = src[i];
}
__device__ __forceinline__ void ldbias(V32& h, const float* __restrict__ b) {
#pragma unroll
    for (int j = 0; j < FF; j++) h.f[j] = b[j];
}
__device__ __forceinline__ void relu32(V32& h) {
#pragma unroll
    for (int j = 0; j < FF; j++) h.f[j] = fmaxf(h.f[j], 0.f);
}
__device__ __forceinline__ void red4(float* __restrict__ a, float x, float y, float z, float w) {
    asm volatile("red.global.add.v4.f32 [%0], {%1, %2, %3, %4};" ::"l"(a), "f"(x), "f"(y),
                 "f"(z), "f"(w)
                 : "memory");
}
__device__ __forceinline__ void scatter8(float* __restrict__ acc, const V8& o) {
    red4(acc, o.f[0], o.f[1], o.f[2], o.f[3]);
    red4(acc + 4, o.f[4], o.f[5], o.f[6], o.f[7]);
}
__device__ __forceinline__ void store_relu8(float* __restrict__ dst, const V8& o) {
    *(float4*)(dst) = make_float4(fmaxf(o.f[0], 0.f), fmaxf(o.f[1], 0.f), fmaxf(o.f[2], 0.f),
                                  fmaxf(o.f[3], 0.f));
    *(float4*)(dst + 4) = make_float4(fmaxf(o.f[4], 0.f), fmaxf(o.f[5], 0.f),
                                      fmaxf(o.f[6], 0.f), fmaxf(o.f[7], 0.f));
}

// quad layer-2, one 8-column block: o{e} = b1[blk*8..] + h{e} @ w1[:, blk*8 : blk*8+8]
// then scatter + store immediately (keeps o live range minimal)
__device__ __forceinline__ void layer2q_blk8(const V32& h0, const V32& h1, const V32& h2,
                                             const V32& h3, const float* __restrict__ sw1,
                                             const float* __restrict__ sb1, int blk,
                                             float* __restrict__ accbase, const int r[4],
                                             float* __restrict__ ebase, int e0) {
    V8 o0, o1, o2, o3;
#pragma unroll
    for (int j = 0; j < 8; j++) {
        float b = sb1[blk * 8 + j];
        o0.f[j] = b;
        o1.f[j] = b;
        o2.f[j] = b;
        o3.f[j] = b;
    }
#pragma unroll
    for (int k = 0; k < FF; k++) {
        const float* wr = sw1 + k * FF + blk * 8;
        ulonglong2 wa = *(const ulonglong2*)(wr);
        ulonglong2 wb = *(const ulonglong2*)(wr + 4);
        ull v0 = pk2(h0.f[k]), v1 = pk2(h1.f[k]), v2 = pk2(h2.f[k]), v3 = pk2(h3.f[k]);
        ffma2(o0.u[0], v0, wa.x);
        ffma2(o0.u[1], v0, wa.y);
        ffma2(o0.u[2], v0, wb.x);
        ffma2(o0.u[3], v0, wb.y);
        ffma2(o1.u[0], v1, wa.x);
        ffma2(o1.u[1], v1, wa.y);
        ffma2(o1.u[2], v1, wb.x);
        ffma2(o1.u[3], v1, wb.y);
        ffma2(o2.u[0], v2, wa.x);
        ffma2(o2.u[1], v2, wa.y);
        ffma2(o2.u[2], v2, wb.x);
        ffma2(o2.u[3], v2, wb.y);
        ffma2(o3.u[0], v3, wa.x);
        ffma2(o3.u[1], v3, wa.y);
        ffma2(o3.u[2], v3, wb.x);
        ffma2(o3.u[3], v3, wb.y);
    }
    int off = blk * 8;
    scatter8(accbase + (size_t)r[0] * FF + off, o0);
    scatter8(accbase + (size_t)r[1] * FF + off, o1);
    scatter8(accbase + (size_t)r[2] * FF + off, o2);
    scatter8(accbase + (size_t)r[3] * FF + off, o3);
    store_relu8(ebase + (size_t)(e0 + 0) * FF + off, o0);
    store_relu8(ebase + (size_t)(e0 + 1) * FF + off, o1);
    store_relu8(ebase + (size_t)(e0 + 2) * FF + off, o2);
    store_relu8(ebase + (size_t)(e0 + 3) * FF + off, o3);
}

// ---- paired helpers (conv4) ----
__device__ __forceinline__ void fmarow2p(V32& h0, V32& h1, ull v0, ull v1,
                                         const float* __restrict__ wr) {
#pragma unroll
    for (int j = 0; j < 8; j++) {
        ulonglong2 w = *(const ulonglong2*)(wr + j * 4);
        ffma2(h0.u[2 * j + 0], v0, w.x);
        ffma2(h0.u[2 * j + 1], v0, w.y);
        ffma2(h1.u[2 * j + 0], v1, w.x);
        ffma2(h1.u[2 * j + 1], v1, w.y);
    }
}
__device__ __forceinline__ void seg32p(V32& h0, V32& h1, const float* __restrict__ s0,
                                       const float* __restrict__ s1,
                                       const float* __restrict__ ws) {
#pragma unroll
    for (int k = 0; k < FF; k += 4) {
        float4 a = *(const float4*)(s0 + k);
        float4 b = *(const float4*)(s1 + k);
        fmarow2p(h0, h1, pk2(a.x), pk2(b.x), ws + (k + 0) * FF);
        fmarow2p(h0, h1, pk2(a.y), pk2(b.y), ws + (k + 1) * FF);
        fmarow2p(h0, h1, pk2(a.z), pk2(b.z), ws + (k + 2) * FF);
        fmarow2p(h0, h1, pk2(a.w), pk2(b.w), ws + (k + 3) * FF);
    }
}
__device__ __forceinline__ void layer2p(V32& o0, V32& o1, const V32& h0, const V32& h1,
                                        const float* __restrict__ sw1,
                                        const float* __restrict__ sb1) {
    ldbias(o0, sb1);
    ldbias(o1, sb1);
#pragma unroll
    for (int k = 0; k < FF; k++) fmarow2p(o0, o1, pk2(h0.f[k]), pk2(h1.f[k]), sw1 + k * FF);
}

// ---------------- init / finalize ----------------
__global__ void k_init(const float* __restrict__ beta, float* __restrict__ out) {
    int i = blockIdx.x * blockDim.x + threadIdx.x;
    if (i < NN * FF) {
        g_acc1[i] = 0.f;
        g_acc2[i] = 0.f;
        g_acc3[i] = 0.f;
    }
    if (i < NN) g_cnt[i] = 0.f;
    if (i < 3 * NN) out[(size_t)5 * EE + i] = beta[i];
}

__global__ void k_final(int which) {
    int i = blockIdx.x * blockDim.x + threadIdx.x;
    if (i >= NN * FF) return;
    float* acc = (which == 0) ? g_acc1 : (which == 1) ? g_acc2 : g_acc3;
    float c = fmaxf(g_cnt[i >> 5], 1.0f);
    acc[i] = fmaxf(acc[i] / c, 0.0f);
}

// ---------------- conv1 (quad) ----------------
__global__ __launch_bounds__(128) void k_conv1(const float* __restrict__ ea,
                                               const int* __restrict__ eidx,
                                               const float* __restrict__ w10,
                                               const float* __restrict__ b10,
                                               const float* __restrict__ w11,
                                               const float* __restrict__ b11) {
    __shared__ __align__(16) float s_w0[4 * FF];
    __shared__ __align__(16) float s_b0[FF];
    __shared__ __align__(16) float s_w1[FF * FF];
    __shared__ __align__(16) float s_b1[FF];
    int tid = threadIdx.x, nt = blockDim.x;
    cpsh(s_w0, w10, 4 * FF, tid, nt);
    cpsh(s_b0, b10, FF, tid, nt);
    cpsh(s_w1, w11, FF * FF, tid, nt);
    cpsh(s_b1, b11, FF, tid, nt);
    __syncthreads();

    int p = blockIdx.x * nt + tid;
    if (p >= QE) return;
    int e0 = 4 * p;

    float4 a0 = *(const float4*)(ea + (size_t)(e0 + 0) * 4);
    float4 a1 = *(const float4*)(ea + (size_t)(e0 + 1) * 4);
    float4 a2 = *(const float4*)(ea + (size_t)(e0 + 2) * 4);
    float4 a3 = *(const float4*)(ea + (size_t)(e0 + 3) * 4);
    V32 h0, h1, h2, h3;
    ldbias(h0, s_b0);
    ldbias(h1, s_b0);
    ldbias(h2, s_b0);
    ldbias(h3, s_b0);
    fmarow4(h0, h1, h2, h3, pk2(a0.x), pk2(a1.x), pk2(a2.x), pk2(a3.x), s_w0);
    fmarow4(h0, h1, h2, h3, pk2(a0.y), pk2(a1.y), pk2(a2.y), pk2(a3.y), s_w0 + FF);
    fmarow4(h0, h1, h2, h3, pk2(a0.z), pk2(a1.z), pk2(a2.z), pk2(a3.z), s_w0 + 2 * FF);
    fmarow4(h0, h1, h2, h3, pk2(a0.w), pk2(a1.w), pk2(a2.w), pk2(a3.w), s_w0 + 3 * FF);
    relu32(h0);
    relu32(h1);
    relu32(h2);
    relu32(h3);

    int r[4];
#pragma unroll
    for (int e = 0; e < 4; e++) r[e] = eidx[e0 + e];

#pragma unroll
    for (int blk = 0; blk < 4; blk++)
        layer2q_blk8(h0, h1, h2, h3, s_w1, s_b1, blk, g_acc1, r, g_e1, e0);

#pragma unroll
    for (int e = 0; e < 4; e++) atomicAdd(&g_cnt[r[e]], 1.0f);
}

// ---------------- conv2 (quad): in = [x1[r], x1[c], edge_attr, e1] ----------------
__global__ __launch_bounds__(128) void k_conv2(const float* __restrict__ ea,
                                               const int* __restrict__ eidx,
                                               const float* __restrict__ w20,
                                               const float* __restrict__ b20,
                                               const float* __restrict__ w21,
                                               const float* __restrict__ b21) {
    __shared__ __align__(16) float s_w0[100 * FF];
    __shared__ __align__(16) float s_b0[FF];
    __shared__ __align__(16) float s_w1[FF * FF];
    __shared__ __align__(16) float s_b1[FF];
    int tid = threadIdx.x, nt = blockDim.x;
    cpsh(s_w0, w20, 100 * FF, tid, nt);
    cpsh(s_b0, b20, FF, tid, nt);
    cpsh(s_w1, w21, FF * FF, tid, nt);
    cpsh(s_b1, b21, FF, tid, nt);
    __syncthreads();

    int p = blockIdx.x * nt + tid;
    if (p >= QE) return;
    int e0 = 4 * p;

    int r[4], c[4];
#pragma unroll
    for (int e = 0; e < 4; e++) {
        r[e] = eidx[e0 + e];
        c[e] = eidx[EE + e0 + e];
    }

    V32 h0, h1, h2, h3;
    ldbias(h0, s_b0);
    ldbias(h1, s_b0);
    ldbias(h2, s_b0);
    ldbias(h3, s_b0);

    seg32q(h0, h1, h2, h3, g_acc1 + (size_t)r[0] * FF, g_acc1 + (size_t)r[1] * FF,
           g_acc1 + (size_t)r[2] * FF, g_acc1 + (size_t)r[3] * FF, s_w0);
    seg32q(h0, h1, h2, h3, g_acc1 + (size_t)c[0] * FF, g_acc1 + (size_t)c[1] * FF,
           g_acc1 + (size_t)c[2] * FF, g_acc1 + (size_t)c[3] * FF, s_w0 + 32 * FF);
    {
        float4 a0 = *(const float4*)(ea + (size_t)(e0 + 0) * 4);
        float4 a1 = *(const float4*)(ea + (size_t)(e0 + 1) * 4);
        float4 a2 = *(const float4*)(ea + (size_t)(e0 + 2) * 4);
        float4 a3 = *(const float4*)(ea + (size_t)(e0 + 3) * 4);
        fmarow4(h0, h1, h2, h3, pk2(a0.x), pk2(a1.x), pk2(a2.x), pk2(a3.x), s_w0 + 64 * FF);
        fmarow4(h0, h1, h2, h3, pk2(a0.y), pk2(a1.y), pk2(a2.y), pk2(a3.y), s_w0 + 65 * FF);
        fmarow4(h0, h1, h2, h3, pk2(a0.z), pk2(a1.z), pk2(a2.z), pk2(a3.z), s_w0 + 66 * FF);
        fmarow4(h0, h1, h2, h3, pk2(a0.w), pk2(a1.w), pk2(a2.w), pk2(a3.w), s_w0 + 67 * FF);
    }
    seg32q(h0, h1, h2, h3, g_e1 + (size_t)(e0 + 0) * FF, g_e1 + (size_t)(e0 + 1) * FF,
           g_e1 + (size_t)(e0 + 2) * FF, g_e1 + (size_t)(e0 + 3) * FF, s_w0 + 68 * FF);
    relu32(h0);
    relu32(h1);
    relu32(h2);
    relu32(h3);

#pragma unroll
    for (int blk = 0; blk < 4; blk++)
        layer2q_blk8(h0, h1, h2, h3, s_w1, s_b1, blk, g_acc2, r, g_e2, e0);
}

// ---------------- conv3 (quad): in = [x2[r], x1[r], x2[c], x1[c], e2, e1] ----------------
__global__ __launch_bounds__(128) void k_conv3(const int* __restrict__ eidx,
                                               const float* __restrict__ w30,
                                               const float* __restrict__ b30,
                                               const float* __restrict__ w31,
                                               const float* __restrict__ b31) {
    __shared__ __align__(16) float s_w0[192 * FF];
    __shared__ __align__(16) float s_b0[FF];
    __shared__ __align__(16) float s_w1[FF * FF];
    __shared__ __align__(16) float s_b1[FF];
    int tid = threadIdx.x, nt = blockDim.x;
    cpsh(s_w0, w30, 192 * FF, tid, nt);
    cpsh(s_b0, b30, FF, tid, nt);
    cpsh(s_w1, w31, FF * FF, tid, nt);
    cpsh(s_b1, b31, FF, tid, nt);
    __syncthreads();

    int p = blockIdx.x * nt + tid;
    if (p >= QE) return;
    int e0 = 4 * p;

    int r[4], c[4];
#pragma unroll
    for (int e = 0; e < 4; e++) {
        r[e] = eidx[e0 + e];
        c[e] = eidx[EE + e0 + e];
    }

    V32 h0, h1, h2, h3;
    ldbias(h0, s_b0);
    ldbias(h1, s_b0);
    ldbias(h2, s_b0);
    ldbias(h3, s_b0);

    seg32q(h0, h1, h2, h3, g_acc2 + (size_t)r[0] * FF, g_acc2 + (size_t)r[1] * FF,
           g_acc2 + (size_t)r[2] * FF, g_acc2 + (size_t)r[3] * FF, s_w0);
    seg32q(h0, h1, h2, h3, g_acc1 + (size_t)r[0] * FF, g_acc1 + (size_t)r[1] * FF,
           g_acc1 + (size_t)r[2] * FF, g_acc1 + (size_t)r[3] * FF, s_w0 + 32 * FF);
    seg32q(h0, h1, h2, h3, g_acc2 + (size_t)c[0] * FF, g_acc2 + (size_t)c[1] * FF,
           g_acc2 + (size_t)c[2] * FF, g_acc2 + (size_t)c[3] * FF, s_w0 + 64 * FF);
    seg32q(h0, h1, h2, h3, g_acc1 + (size_t)c[0] * FF, g_acc1 + (size_t)c[1] * FF,
           g_acc1 + (size_t)c[2] * FF, g_acc1 + (size_t)c[3] * FF, s_w0 + 96 * FF);
    seg32q(h0, h1, h2, h3, g_e2 + (size_t)(e0 + 0) * FF, g_e2 + (size_t)(e0 + 1) * FF,
           g_e2 + (size_t)(e0 + 2) * FF, g_e2 + (size_t)(e0 + 3) * FF, s_w0 + 128 * FF);
    seg32q(h0, h1, h2, h3, g_e1 + (size_t)(e0 + 0) * FF, g_e1 + (size_t)(e0 + 1) * FF,
           g_e1 + (size_t)(e0 + 2) * FF, g_e1 + (size_t)(e0 + 3) * FF, s_w0 + 160 * FF);
    relu32(h0);
    relu32(h1);
    relu32(h2);
    relu32(h3);

#pragma unroll
    for (int blk = 0; blk < 4; blk++)
        layer2q_blk8(h0, h1, h2, h3, s_w1, s_b1, blk, g_acc3, r, g_e3, e0);
}

// ---------------- conv4 + heads (pair, proven layout) ----------------
__global__ __launch_bounds__(128) void k_conv4(
    const float* __restrict__ ea, const int* __restrict__ eidx,
    const float* __restrict__ w40, const float* __restrict__ b40,
    const float* __restrict__ w41, const float* __restrict__ b41,
    const float* __restrict__ wl01, const float* __restrict__ bl01,
    const float* __restrict__ wl02, const float* __restrict__ bl02,
    const float* __restrict__ wl1, const float* __restrict__ bl1,
    const float* __restrict__ wl2, const float* __restrict__ bl2, float* __restrict__ out) {
    __shared__ __align__(16) float s_w0[192 * FF];
    __shared__ __align__(16) float s_b0[FF];
    __shared__ __align__(16) float s_w1[FF * FF];
    __shared__ __align__(16) float s_b1[FF];
    __shared__ __align__(16) float s_w01[FF * FF];
    __shared__ __align__(16) float s_b01[FF];
    __shared__ __align__(16) float s_w02[FF * FF];
    __shared__ __align__(16) float s_b02[FF];
    __shared__ __align__(16) float s_wl1[FF * 4];
    __shared__ __align__(16) float s_wl2[FF];
    __shared__ float s_bl1[4];
    __shared__ float s_bl2;
    int tid = threadIdx.x, nt = blockDim.x;
    cpsh(s_w0, w40, 192 * FF, tid, nt);
    cpsh(s_b0, b40, FF, tid, nt);
    cpsh(s_w1, w41, FF * FF, tid, nt);
    cpsh(s_b1, b41, FF, tid, nt);
    cpsh(s_w01, wl01, FF * FF, tid, nt);
    cpsh(s_b01, bl01, FF, tid, nt);
    cpsh(s_w02, wl02, FF * FF, tid, nt);
    cpsh(s_b02, bl02, FF, tid, nt);
    cpsh(s_wl1, wl1, FF * 4, tid, nt);
    cpsh(s_wl2, wl2, FF, tid, nt);
    if (tid < 4) s_bl1[tid] = bl1[tid];
    if (tid == 0) s_bl2 = bl2[0];
    __syncthreads();

    int p = blockIdx.x * nt + tid;
    if (p >= HALF_E) return;
    int e0 = 2 * p, e1 = 2 * p + 1;

    int r0 = eidx[e0], c0 = eidx[EE + e0];
    int r1 = eidx[e1], c1 = eidx[EE + e1];
    V32 h0, h1;
    ldbias(h0, s_b0);
    ldbias(h1, s_b0);
    seg32p(h0, h1, g_acc3 + (size_t)r0 * FF, g_acc3 + (size_t)r1 * FF, s_w0);
    seg32p(h0, h1, g_acc2 + (size_t)r0 * FF, g_acc2 + (size_t)r1 * FF, s_w0 + 32 * FF);
    seg32p(h0, h1, g_acc3 + (size_t)c0 * FF, g_acc3 + (size_t)c1 * FF, s_w0 + 64 * FF);
    seg32p(h0, h1, g_acc2 + (size_t)c0 * FF, g_acc2 + (size_t)c1 * FF, s_w0 + 96 * FF);
    seg32p(h0, h1, g_e3 + (size_t)e0 * FF, g_e3 + (size_t)e1 * FF, s_w0 + 128 * FF);
    seg32p(h0, h1, g_e2 + (size_t)e0 * FF, g_e2 + (size_t)e1 * FF, s_w0 + 160 * FF);
    relu32(h0);
    relu32(h1);

    V32 e40, e41;
    layer2p(e40, e41, h0, h1, s_w1, s_b1);
    relu32(e40);
    relu32(e41);

    layer2p(h0, h1, e40, e41, s_w01, s_b01);

#pragma unroll
    for (int side = 0; side < 2; side++) {
        const V32& hh = side ? h1 : h0;
        int e = side ? e1 : e0;
        float4 a = *(const float4*)(ea + (size_t)e * 4);
        float ex0 = s_bl1[0] + a.x, ex1 = s_bl1[1] + a.y;
        float ex2 = s_bl1[2] + a.z, ex3 = s_bl1[3] + a.w;
#pragma unroll
        for (int j = 0; j < FF; j++) {
            float4 w = *(const float4*)(s_wl1 + j * 4);
            ex0 += hh.f[j] * w.x;
            ex1 += hh.f[j] * w.y;
            ex2 += hh.f[j] * w.z;
            ex3 += hh.f[j] * w.w;
        }
        float nrm = sqrtf(ex0 * ex0 + ex1 * ex1 + ex2 * ex2 + ex3 * ex3);
        float inv = 1.0f / fmaxf(nrm, 1e-12f);
        *(float4*)(out + (size_t)EE + (size_t)e * 4) =
            make_float4(ex0 * inv, ex1 * inv, ex2 * inv, ex3 * inv);
    }

    layer2p(h0, h1, e40, e41, s_w02, s_b02);
#pragma unroll
    for (int side = 0; side < 2; side++) {
        const V32& hh = side ? h1 : h0;
        int e = side ? e1 : e0;
        float z = s_bl2;
#pragma unroll
        for (int j = 0; j < FF; j++) z += hh.f[j] * s_wl2[j];
        out[e] = 1.0f / (1.0f + expf(-z));
    }
}

// ---------------- launch ----------------
extern "C" void kernel_launch(void* const* d_in, const int* in_sizes, int n_in,
                              void* d_out, int out_size) {
    const int* eidx = (const int*)d_in[1];
    const float* ea = (const float*)d_in[2];
    const float* beta = (const float*)d_in[3];
    const float* w10 = (const float*)d_in[4];
    const float* b10 = (const float*)d_in[5];
    const float* w11 = (const float*)d_in[6];
    const float* b11 = (const float*)d_in[7];
    const float* w20 = (const float*)d_in[8];
    const float* b20 = (const float*)d_in[9];
    const float* w21 = (const float*)d_in[10];
    const float* b21 = (const float*)d_in[11];
    const float* w30 = (const float*)d_in[12];
    const float* b30 = (const float*)d_in[13];
    const float* w31 = (const float*)d_in[14];
    const float* b31 = (const float*)d_in[15];
    const float* w40 = (const float*)d_in[16];
    const float* b40 = (const float*)d_in[17];
    const float* w41 = (const float*)d_in[18];
    const float* b41 = (const float*)d_in[19];
    const float* wl01 = (const float*)d_in[20];
    const float* bl01 = (const float*)d_in[21];
    const float* wl02 = (const float*)d_in[22];
    const float* bl02 = (const float*)d_in[23];
    const float* wl1 = (const float*)d_in[24];
    const float* bl1 = (const float*)d_in[25];
    const float* wl2 = (const float*)d_in[26];
    const float* bl2 = (const float*)d_in[27];
    float* out = (float*)d_out;

    const int T = 256;
    const int gridNF = (NN * FF + T - 1) / T;
    const int TB = 128;
    const int gridQ = (QE + TB - 1) / TB;
    const int gridP = (HALF_E + TB - 1) / TB;

    k_init<<<gridNF, T>>>(beta, out);
    k_conv1<<<gridQ, TB>>>(ea, eidx, w10, b10, w11, b11);
    k_final<<<gridNF, T>>>(0);
    k_conv2<<<gridQ, TB>>>(ea, eidx, w20, b20, w21, b21);
    k_final<<<gridNF, T>>>(1);
    k_conv3<<<gridQ, TB>>>(eidx, w30, b30, w31, b31);
    k_final<<<gridNF, T>>>(2);
    k_conv4<<<gridP, TB>>>(ea, eidx, w40, b40, w41, b41, wl01, bl01, wl02, bl02,
                           wl1, bl1, wl2, bl2, out);
}